// round 17
// baseline (speedup 1.0000x reference)
#include <cuda_runtime.h>
#include <cstdint>

#define QN     1024
#define NDATA  50000
#define DIM    512
#define KNN    10

#define NCAND  8               // candidates kept per (query, 128-pt chunk)
#define CHPTS  128
#define NCHUNK 391              // ceil(50000/128)
#define NC     (NCHUNK * NCAND) // 3128 candidates per query
#define TOPM   32               // rescored exactly

#define FINF 3.4e38f

// ---------------- device scratch (no allocs allowed) ----------------
__device__ float g_d2[NDATA];
__device__ float g_cand_val[(size_t)QN * NC];           // 12.8 MB
__device__ int   g_cand_idx[(size_t)QN * NC];           // 12.8 MB
__device__ int   g_t64;

// ---------------- small kernels ----------------
__global__ void probe_targets_v16(const void* __restrict__ targets) {
    if (threadIdx.x == 0) {
        const long long* t = (const long long*)targets;
        int ok = 1;
        for (int i = 0; i < 64; i++) { long long v = t[i]; if (v < 0 || v >= 100) { ok = 0; break; } }
        g_t64 = ok;
    }
}

__global__ void d2_kernel_v16(const float* __restrict__ data) {
    int warp = (blockIdx.x * blockDim.x + threadIdx.x) >> 5;
    int lane = threadIdx.x & 31;
    if (warp >= NDATA) return;
    const float4* row = (const float4*)(data + (size_t)warp * DIM);
    float acc = 0.f;
#pragma unroll
    for (int i = 0; i < DIM / 4 / 32; i++) {
        float4 v = row[lane + i * 32];
        acc += v.x * v.x + v.y * v.y + v.z * v.z + v.w * v.w;
    }
#pragma unroll
    for (int o = 16; o > 0; o >>= 1) acc += __shfl_down_sync(0xffffffffu, acc, o);
    if (lane == 0) g_d2[warp] = acc;
}

// ---------------- phase A: exact fp32 chunk GEMM + fused per-chunk top-8 ----
// CTA: 128 queries x 128 data points (one chunk). Mainloop is R5's proven
// 128x128x16 fp32 tiled GEMM (8x8 microtiles, 256 threads, rel_err 0.0).
// Epilogue stages raw dot products into sc[128][36] slabs of 32 columns and
// runs the SAME reader / top-8 / merge / candidate-write as the R14 filter.
__global__ __launch_bounds__(256, 2) void knn_chunk_gemm_v16(const float* __restrict__ X,
                                                             const float* __restrict__ Dm) {
    __shared__ __align__(16) char smem_raw[28928];
    float (*As)[132] = (float(*)[132])smem_raw;            // [16][132]
    float (*Bs)[132] = (float(*)[132])(smem_raw + 8448);   // [16][132]

    const int t     = threadIdx.x;
    const int chunk = blockIdx.x;
    const int m0    = blockIdx.y * 128;
    const int nbase = chunk * CHPTS;
    const int ty    = t >> 4;   // 0..15 (m dim, rows ty*8..ty*8+7)
    const int tx    = t & 15;   // 0..15 (n dim, cols tx*8..tx*8+7)

    float acc[8][8];
#pragma unroll
    for (int i = 0; i < 8; i++)
#pragma unroll
        for (int j = 0; j < 8; j++) acc[i][j] = 0.f;

    for (int k0 = 0; k0 < DIM; k0 += 16) {
        // load X tile [128 x 16] -> As[k][m]
#pragma unroll
        for (int it = 0; it < 2; it++) {
            int li  = t + it * 256;          // 0..511 float4 slots
            int row = li >> 2;               // 0..127
            int c4  = li & 3;                // 0..3
            float4 v = *(const float4*)(X + (size_t)(m0 + row) * DIM + k0 + c4 * 4);
            As[c4 * 4 + 0][row] = v.x;
            As[c4 * 4 + 1][row] = v.y;
            As[c4 * 4 + 2][row] = v.z;
            As[c4 * 4 + 3][row] = v.w;
        }
        // load data tile [128 x 16] -> Bs[k][n] (guard N tail)
#pragma unroll
        for (int it = 0; it < 2; it++) {
            int li  = t + it * 256;
            int row = li >> 2;
            int c4  = li & 3;
            int n   = nbase + row;
            float4 v = make_float4(0.f, 0.f, 0.f, 0.f);
            if (n < NDATA) v = *(const float4*)(Dm + (size_t)n * DIM + k0 + c4 * 4);
            Bs[c4 * 4 + 0][row] = v.x;
            Bs[c4 * 4 + 1][row] = v.y;
            Bs[c4 * 4 + 2][row] = v.z;
            Bs[c4 * 4 + 3][row] = v.w;
        }
        __syncthreads();

#pragma unroll
        for (int kk = 0; kk < 16; kk++) {
            float4 a0 = *(const float4*)&As[kk][ty * 8];
            float4 a1 = *(const float4*)&As[kk][ty * 8 + 4];
            float4 b0 = *(const float4*)&Bs[kk][tx * 8];
            float4 b1 = *(const float4*)&Bs[kk][tx * 8 + 4];
            float a[8] = {a0.x, a0.y, a0.z, a0.w, a1.x, a1.y, a1.z, a1.w};
            float b[8] = {b0.x, b0.y, b0.z, b0.w, b1.x, b1.y, b1.z, b1.w};
#pragma unroll
            for (int i = 0; i < 8; i++)
#pragma unroll
                for (int j = 0; j < 8; j++) acc[i][j] += a[i] * b[j];
        }
        __syncthreads();
    }

    // ---- epilogue: stage raw dots into sc[128][36] slabs; reader identical
    // to the R14 filter (score = d2[n] - 2*dot applied at read time). ----
    float* sc = (float*)smem_raw;                  // [128][36] floats
    float rv[NCAND]; int ri[NCAND];
#pragma unroll
    for (int i = 0; i < NCAND; i++) { rv[i] = FINF; ri[i] = 0x7fffffff; }
    float worst = FINF;

    const int rrow = t >> 1;                       // reader row (2 thr/row)
    const int rc0  = (t & 1) * 16;

    for (int s = 0; s < 4; s++) {
        // writers: threads with tx in [4s, 4s+4) own this slab's 32 columns
        if ((tx >> 2) == s) {
            int cb = (tx & 3) * 8;                 // slab-local col base
#pragma unroll
            for (int i = 0; i < 8; i++)
#pragma unroll
                for (int j = 0; j < 8; j++)
                    sc[(ty * 8 + i) * 36 + cb + j] = acc[i][j];
        }
        __syncthreads();
        // readers: score = d2[n] - 2*dot, streaming top-8 over 16 columns
#pragma unroll
        for (int c = 0; c < 16; c++) {
            int n = nbase + s * 32 + rc0 + c;
            float v = FINF;
            if (n < NDATA) v = __ldg(&g_d2[n]) - 2.f * sc[rrow * 36 + rc0 + c];
            if (v < worst) {
                rv[NCAND - 1] = v; ri[NCAND - 1] = n;
#pragma unroll
                for (int p = NCAND - 1; p > 0; p--) {
                    if (rv[p] < rv[p - 1]) {
                        float tv = rv[p]; rv[p] = rv[p - 1]; rv[p - 1] = tv;
                        int ti = ri[p]; ri[p] = ri[p - 1]; ri[p - 1] = ti;
                    }
                }
                worst = rv[NCAND - 1];
            }
        }
        __syncthreads();
    }

    // pairwise merge of the two per-row lists, write NCAND candidates
    float* mbv = (float*)(smem_raw + 20480);       // [128][8] floats
    int*   mbi = (int*)(smem_raw + 24576);         // [128][8] ints
    if (t & 1) {
#pragma unroll
        for (int r = 0; r < NCAND; r++) { mbv[rrow * NCAND + r] = rv[r]; mbi[rrow * NCAND + r] = ri[r]; }
    }
    __syncthreads();
    if (!(t & 1)) {
        float ov[NCAND]; int oi[NCAND];
#pragma unroll
        for (int r = 0; r < NCAND; r++) { ov[r] = mbv[rrow * NCAND + r]; oi[r] = mbi[rrow * NCAND + r]; }
        size_t base = ((size_t)(m0 + rrow) * NCHUNK + chunk) * NCAND;
        int ai = 0, bi = 0;
#pragma unroll
        for (int r = 0; r < NCAND; r++) {
            bool ta = (rv[ai] < ov[bi]) || (rv[ai] == ov[bi] && ri[ai] < oi[bi]);
            if (ta) { g_cand_val[base + r] = rv[ai]; g_cand_idx[base + r] = ri[ai]; ai++; }
            else    { g_cand_val[base + r] = ov[bi]; g_cand_idx[base + r] = oi[bi]; bi++; }
        }
    }
}

// ---------------- phase B: merge -> exact rescore -> mode ----------------
__global__ void knn_merge_v16(const float* __restrict__ X, const float* __restrict__ data,
                              const void* __restrict__ targets, float* __restrict__ out) {
    const int q    = blockIdx.x;
    const int tid  = threadIdx.x;
    const int wid  = tid >> 5;
    const int lane = tid & 31;

    __shared__ unsigned long long keys[NC];
    __shared__ unsigned long long wmin[8];
    __shared__ unsigned long long sbest;
    __shared__ int   cidx[TOPM];
    __shared__ float cval[TOPM];
    __shared__ __align__(16) float sX[DIM];

    // candidates as orderable u64 keys (val asc, idx tiebreak)
    for (int i = tid; i < NC; i += 256) {
        float v = g_cand_val[(size_t)q * NC + i];
        int  ix = g_cand_idx[(size_t)q * NC + i];
        uint32_t b = __float_as_uint(v);
        b = (b & 0x80000000u) ? ~b : (b | 0x80000000u);
        keys[i] = ((unsigned long long)b << 32) | (uint32_t)ix;
    }
    if (tid < 128) ((float4*)sX)[tid] = ((const float4*)(X + (size_t)q * DIM))[tid];
    __syncthreads();

    // top-32 of the candidate pool
    for (int r = 0; r < TOPM; r++) {
        unsigned long long lm = ~0ull;
        for (int i = tid; i < NC; i += 256) { unsigned long long k = keys[i]; if (k < lm) lm = k; }
#pragma unroll
        for (int o = 16; o > 0; o >>= 1) {
            unsigned long long x = __shfl_down_sync(0xffffffffu, lm, o);
            if (x < lm) lm = x;
        }
        if (lane == 0) wmin[wid] = lm;
        __syncthreads();
        if (tid == 0) {
            unsigned long long b = ~0ull;
#pragma unroll
            for (int w = 0; w < 8; w++) if (wmin[w] < b) b = wmin[w];
            sbest = b;
            cidx[r] = (int)(b & 0xffffffffu);
        }
        __syncthreads();
        unsigned long long best = sbest;
        for (int i = tid; i < NC; i += 256) if (keys[i] == best) keys[i] = ~0ull;
        __syncthreads();
    }

    // exact fp32 rescore of the 32 candidates (4 per warp)
#pragma unroll
    for (int i = 0; i < TOPM / 8; i++) {
        int c = wid * (TOPM / 8) + i;
        int n = cidx[c];
        const float4* dr = (const float4*)(data + (size_t)n * DIM);
        const float4* xr = (const float4*)sX;
        float acc = 0.f;
#pragma unroll
        for (int j = 0; j < 4; j++) {
            float4 xv = xr[lane + 32 * j];
            float4 dv = dr[lane + 32 * j];
            acc += xv.x * dv.x + xv.y * dv.y + xv.z * dv.z + xv.w * dv.w;
        }
#pragma unroll
        for (int o = 16; o > 0; o >>= 1) acc += __shfl_down_sync(0xffffffffu, acc, o);
        if (lane == 0) cval[c] = g_d2[n] - 2.f * acc;
    }
    __syncthreads();

    // exact top-10 (ties -> smaller idx), labels, mode (ties -> smaller class)
    if (tid == 0) {
        bool used[TOPM];
#pragma unroll
        for (int c = 0; c < TOPM; c++) used[c] = false;
        int labs[KNN];
        for (int r = 0; r < KNN; r++) {
            float bv = FINF; int bi = 0x7fffffff, bc = 0;
            for (int c = 0; c < TOPM; c++) {
                if (used[c]) continue;
                if (cval[c] < bv || (cval[c] == bv && cidx[c] < bi)) { bv = cval[c]; bi = cidx[c]; bc = c; }
            }
            used[bc] = true;
            labs[r] = g_t64 ? (int)((const long long*)targets)[bi]
                            : ((const int*)targets)[bi];
        }
        int bestLab = 1 << 30, bestC = 0;
#pragma unroll
        for (int i = 0; i < KNN; i++) {
            int li = labs[i], c = 0;
#pragma unroll
            for (int j = 0; j < KNN; j++) c += (labs[j] == li);
            if (c > bestC || (c == bestC && li < bestLab)) { bestC = c; bestLab = li; }
        }
        out[q] = (float)bestLab;
    }
}

// ---------------------------------------------------------------------------
extern "C" void kernel_launch(void* const* d_in, const int* in_sizes, int n_in,
                              void* d_out, int out_size) {
    const float* X       = (const float*)d_in[0];
    const float* data    = (const float*)d_in[1];
    const void*  targets = (const void*)d_in[2];
    for (int i = 0; i < n_in && i < 3; i++) {
        if (in_sizes[i] == QN * DIM)          X       = (const float*)d_in[i];
        else if (in_sizes[i] == NDATA * DIM)  data    = (const float*)d_in[i];
        else if (in_sizes[i] == NDATA)        targets = (const void*)d_in[i];
    }
    float* out = (float*)d_out;
    (void)out_size;

    probe_targets_v16<<<1, 32>>>(targets);
    d2_kernel_v16<<<(NDATA * 32 + 255) / 256, 256>>>(data);

    dim3 gf(NCHUNK, QN / 128);
    knn_chunk_gemm_v16<<<gf, 256>>>(X, data);

    knn_merge_v16<<<QN, 256>>>(X, data, targets, out);
}